// round 6
// baseline (speedup 1.0000x reference)
#include <cuda_runtime.h>
#include <cuda_bf16.h>
#include <cstdint>

// custom_loss_57956288692862
// x: [16384,1024] fp32 -> 4096 groups of 4 rows: q=4b+0, a=4b+1, dead=4b+2, c=4b+3
// target: [2,4096] int32
// out fp32[4097]: out[0]=mean loss, out[1+b]=eq flag
//
// Software-pipelined: each warp owns 2 groups, processed as 4 stages of 12
// front-batched LDG.128 with next-stage loads always issued BEFORE consuming
// the current stage. Group g1's loads fly during g0's shuffle/epilogue, so the
// warp has loads outstanding ~80% of its lifetime (R5's convoy dead-phase fix).
// Single kernel: per-CTA partials + last-CTA mean (ticket counter, reset each
// launch for graph-replay determinism).

#define NB      4096
#define D       1024
#define THREADS 128
#define GRID    512            // 512 CTAs x 4 warps = 2048 warps x 2 groups = 4096
#define WARPS_TOTAL 2048

__device__ float        g_partials[GRID];
__device__ unsigned int g_count;    // zero-init; last CTA resets it every launch

// Issue 12 coalesced LDG.128 for one stage (half a group: 512B/row x 3 rows)
#define LOAD_STAGE(buf, gptr, stage)                                   \
    do {                                                               \
        const int j0_ = (stage) * 4;                                   \
        _Pragma("unroll")                                              \
        for (int j = 0; j < 4; j++) {                                  \
            const int idx_ = lid + 32 * (j0_ + j);                     \
            (buf)[j]     = (gptr)[idx_];          /* q row */          \
            (buf)[4 + j] = (gptr)[256 + idx_];    /* a row */          \
            (buf)[8 + j] = (gptr)[768 + idx_];    /* c row */          \
        }                                                              \
    } while (0)

// Accumulate 6 sums from one stage buffer
#define FMA_STAGE(buf, nq, na, nc, qa, ac, qc)                                        \
    do {                                                                              \
        _Pragma("unroll")                                                             \
        for (int j = 0; j < 4; j++) {                                                 \
            const float4 q_ = (buf)[j], a_ = (buf)[4 + j], c_ = (buf)[8 + j];         \
            nq = fmaf(q_.x, q_.x, nq); nq = fmaf(q_.y, q_.y, nq);                     \
            nq = fmaf(q_.z, q_.z, nq); nq = fmaf(q_.w, q_.w, nq);                     \
            na = fmaf(a_.x, a_.x, na); na = fmaf(a_.y, a_.y, na);                     \
            na = fmaf(a_.z, a_.z, na); na = fmaf(a_.w, a_.w, na);                     \
            nc = fmaf(c_.x, c_.x, nc); nc = fmaf(c_.y, c_.y, nc);                     \
            nc = fmaf(c_.z, c_.z, nc); nc = fmaf(c_.w, c_.w, nc);                     \
            qa = fmaf(q_.x, a_.x, qa); qa = fmaf(q_.y, a_.y, qa);                     \
            qa = fmaf(q_.z, a_.z, qa); qa = fmaf(q_.w, a_.w, qa);                     \
            ac = fmaf(a_.x, c_.x, ac); ac = fmaf(a_.y, c_.y, ac);                     \
            ac = fmaf(a_.z, c_.z, ac); ac = fmaf(a_.w, c_.w, ac);                     \
            qc = fmaf(q_.x, c_.x, qc); qc = fmaf(q_.y, c_.y, qc);                     \
            qc = fmaf(q_.z, c_.z, qc); qc = fmaf(q_.w, c_.w, qc);                     \
        }                                                                             \
    } while (0)

__device__ __forceinline__ float finish_group(
    float nq, float na, float nc, float qa, float ac, float qc,
    int t0i, int t1i, int b, float* __restrict__ out, int out_size, int lid)
{
    // Warp butterfly (6 chains)
    #pragma unroll
    for (int off = 16; off > 0; off >>= 1) {
        nq += __shfl_xor_sync(0xFFFFFFFFu, nq, off);
        na += __shfl_xor_sync(0xFFFFFFFFu, na, off);
        nc += __shfl_xor_sync(0xFFFFFFFFu, nc, off);
        qa += __shfl_xor_sync(0xFFFFFFFFu, qa, off);
        ac += __shfl_xor_sync(0xFFFFFFFFu, ac, off);
        qc += __shfl_xor_sync(0xFFFFFFFFu, qc, off);
    }
    float loss = 0.0f;
    if (lid == 0) {
        float iq = 1.0f / fmaxf(sqrtf(nq), 1e-12f);
        float ia = 1.0f / fmaxf(sqrtf(na), 1e-12f);
        float ic = 1.0f / fmaxf(sqrtf(nc), 1e-12f);

        float dqa = qa * iq * ia;
        float dac = ac * ia * ic;
        float dqc = qc * iq * ic;

        float t0 = (float)t0i;
        float t1 = (float)t1i;

        float eqa = __expf(dqa);
        float eac = __expf(dac);
        float eqc = __expf(dqc);

        float up   = fmaxf((1.0f - t0) * eqa + (1.0f - t1) * eqc, 1e-8f);
        float down = fmaxf(t0 * eqa + t1 * eqc, 1e-8f);

        loss = __logf(up + eac) - __logf(down);

        int correct = (dqa > dqc) ? 1 : 0;
        float eq = (correct == t0i) ? 1.0f : 0.0f;
        if (1 + b < out_size) out[1 + b] = eq;
    }
    return loss;
}

__global__ __launch_bounds__(THREADS)
void loss_kernel(const float* __restrict__ x,
                 const int* __restrict__ target,
                 float* __restrict__ out,
                 int out_size) {
    const int t   = threadIdx.x;
    const int wid = t >> 5;
    const int lid = t & 31;
    const int warpGlobal = blockIdx.x * 4 + wid;
    const int b0 = warpGlobal;                 // group 0
    const int b1 = warpGlobal + WARPS_TOTAL;   // group 1

    // Prefetch targets for both groups (latency hidden under row loads)
    int t00 = 0, t01 = 0, t10 = 0, t11 = 0;
    if (lid == 0) {
        t00 = __ldg(target + b0);
        t01 = __ldg(target + NB + b0);
        t10 = __ldg(target + b1);
        t11 = __ldg(target + NB + b1);
    }

    const float4* __restrict__ g0 =
        reinterpret_cast<const float4*>(x + (size_t)b0 * (4 * D));
    const float4* __restrict__ g1 =
        reinterpret_cast<const float4*>(x + (size_t)b1 * (4 * D));

    float4 bufA[12], bufB[12];

    // ---- Pipelined schedule: always 12-24 LDG.128 in flight ----
    LOAD_STAGE(bufA, g0, 0);                       // S0 -> A
    LOAD_STAGE(bufB, g0, 1);                       // S1 -> B

    float nq0 = 0.f, na0 = 0.f, nc0 = 0.f, qa0 = 0.f, ac0 = 0.f, qc0 = 0.f;
    FMA_STAGE(bufA, nq0, na0, nc0, qa0, ac0, qc0); // consume S0

    LOAD_STAGE(bufA, g1, 0);                       // S2 -> A (g1 first half)
    FMA_STAGE(bufB, nq0, na0, nc0, qa0, ac0, qc0); // consume S1

    LOAD_STAGE(bufB, g1, 1);                       // S3 -> B (g1 second half)

    // g0 reduce + epilogue runs while S2/S3 loads are in flight
    float locLoss = finish_group(nq0, na0, nc0, qa0, ac0, qc0,
                                 t00, t01, b0, out, out_size, lid);

    float nq1 = 0.f, na1 = 0.f, nc1 = 0.f, qa1 = 0.f, ac1 = 0.f, qc1 = 0.f;
    FMA_STAGE(bufA, nq1, na1, nc1, qa1, ac1, qc1); // consume S2
    FMA_STAGE(bufB, nq1, na1, nc1, qa1, ac1, qc1); // consume S3

    locLoss += finish_group(nq1, na1, nc1, qa1, ac1, qc1,
                            t10, t11, b1, out, out_size, lid);

    // ---- Per-CTA aggregation + last-CTA mean ----
    __shared__ float s_loss[4];
    if (lid == 0) s_loss[wid] = locLoss;
    __syncthreads();

    __shared__ bool s_last;
    if (t == 0) {
        g_partials[blockIdx.x] = s_loss[0] + s_loss[1] + s_loss[2] + s_loss[3];
        __threadfence();
        unsigned int ticket = atomicAdd(&g_count, 1u);
        s_last = (ticket == GRID - 1);
    }
    __syncthreads();

    if (s_last) {
        __threadfence();   // acquire: see all partials
        float sum = 0.f;
        #pragma unroll
        for (int i = 0; i < GRID / THREADS; i++)   // 4 per thread
            sum += g_partials[t + i * THREADS];

        #pragma unroll
        for (int off = 16; off > 0; off >>= 1)
            sum += __shfl_xor_sync(0xFFFFFFFFu, sum, off);
        __shared__ float s_red[4];
        if (lid == 0) s_red[wid] = sum;
        __syncthreads();
        if (t == 0) {
            out[0] = (s_red[0] + s_red[1] + s_red[2] + s_red[3]) * (1.0f / (float)NB);
            g_count = 0;   // reset for next graph replay
        }
    }
}

extern "C" void kernel_launch(void* const* d_in, const int* in_sizes, int n_in,
                              void* d_out, int out_size) {
    const float* x      = (const float*)d_in[0];
    const int*   target = (const int*)d_in[1];
    float*       out    = (float*)d_out;

    loss_kernel<<<GRID, THREADS>>>(x, target, out, out_size);
}